// round 14
// baseline (speedup 1.0000x reference)
#include <cuda_runtime.h>

#define Bz 8
#define Hh 384
#define Ww 384
#define HW (384*384)
#define COILS 16

__device__ float g_ximg[Bz*2*HW];        // (B,2,H,W): real/imag planes
__device__ float g_gram[Bz*27*27];       // per-batch 27x27 Gram (block-upper-triangle valid)
__device__ float g_weff[Bz*2*2*9];       // per-batch effective 2->2 3x3 conv weights

__constant__ unsigned char cPU[45] = {0,0,0,0,0,0,0,0,0, 1,1,1,1,1,1,1,1, 2,2,2,2,2,2,2,
                                      3,3,3,3,3,3, 4,4,4,4,4, 5,5,5,5, 6,6,6, 7,7, 8};
__constant__ unsigned char cPV[45] = {0,1,2,3,4,5,6,7,8, 1,2,3,4,5,6,7,8, 2,3,4,5,6,7,8,
                                      3,4,5,6,7,8, 4,5,6,7,8, 5,6,7,8, 6,7,8, 7,8, 8};

// ---------------- K1: coil-combine (float4, 2 px/thread) + zero gram/weff ----------------
__global__ __launch_bounds__(256) void k_coil_reduce(const float* __restrict__ x,
                                                     const float* __restrict__ sens){
    int idx = blockIdx.x*blockDim.x + threadIdx.x;   // over Bz*HW/2
    if (idx < Bz*729) g_gram[idx] = 0.f;
    if (idx < Bz*36)  g_weff[idx] = 0.f;
    int b = idx / (HW/2);
    int h = idx - b*(HW/2);
    const float4* xq = reinterpret_cast<const float4*>(x)    + (size_t)b*COILS*(HW/2) + h;
    const float4* sq = reinterpret_cast<const float4*>(sens) + (size_t)b*COILS*(HW/2) + h;
    float re0=0.f, im0=0.f, re1=0.f, im1=0.f;
    #pragma unroll
    for (int c = 0; c < COILS; c++){
        float4 a = __ldg(xq + (size_t)c*(HW/2));
        float4 s = __ldg(sq + (size_t)c*(HW/2));
        re0 += a.x*s.x + a.y*s.y;  im0 += a.y*s.x - a.x*s.y;
        re1 += a.z*s.z + a.w*s.w;  im1 += a.w*s.z - a.z*s.w;
    }
    float2* pr = reinterpret_cast<float2*>(g_ximg + (size_t)(b*2+0)*HW);
    float2* pi = reinterpret_cast<float2*>(g_ximg + (size_t)(b*2+1)*HW);
    pr[h] = make_float2(re0, re1);
    pi[h] = make_float2(im0, im1);
}

// ---------------- K2: 27x27 Gram via sliding-window (reads L2-resident ximg) ----------------
__global__ __launch_bounds__(256) void k_gram(const float* __restrict__ e){
    __shared__ float sm[3*34*37];     // 3 planes, 34x34 tile+halo, row stride 37
    int b   = blockIdx.z;
    int ty0 = blockIdx.y*32, tx0 = blockIdx.x*32;
    int tid = threadIdx.x;

    for (int i = tid; i < 3*34*34; i += 256){
        int pl = i / 1156; int r = i - pl*1156;
        int y = r / 34, xx = r - y*34;
        int gy = ty0 + y - 1, gx = tx0 + xx - 1;
        float v = 0.f;
        if (gy >= 0 && gy < Hh && gx >= 0 && gx < Ww){
            int gp = gy*Ww + gx;
            v = (pl < 2) ? g_ximg[(size_t)(b*2+pl)*HW + gp] : __ldg(e + (size_t)b*HW + gp);
        }
        sm[pl*1258 + y*37 + xx] = v;
    }
    __syncthreads();

    int lane = tid & 31;
    float* gb = g_gram + b*729;
    for (int task = tid; task < 1440; task += 256){
        int pair = task >> 5;
        int y    = task & 31;
        int bu = cPU[pair], bv = cPV[pair];
        const float* ru = sm + (bu/3)*1258 + (y + (bu%3))*37;
        const float* rv = sm + (bv/3)*1258 + (y + (bv%3))*37;
        float u0 = ru[0], u1 = ru[1];
        float v0 = rv[0], v1 = rv[1];
        float a00=0,a01=0,a02=0,a10=0,a11=0,a12=0,a20=0,a21=0,a22=0;
        #pragma unroll
        for (int xx = 0; xx < 32; xx++){
            float u2 = ru[xx+2], v2 = rv[xx+2];
            a00 += u0*v0; a01 += u0*v1; a02 += u0*v2;
            a10 += u1*v0; a11 += u1*v1; a12 += u1*v2;
            a20 += u2*v0; a21 += u2*v1; a22 += u2*v2;
            u0 = u1; u1 = u2; v0 = v1; v1 = v2;
        }
        #pragma unroll
        for (int s = 16; s > 0; s >>= 1){
            a00 += __shfl_xor_sync(0xffffffffu, a00, s);
            a01 += __shfl_xor_sync(0xffffffffu, a01, s);
            a02 += __shfl_xor_sync(0xffffffffu, a02, s);
            a10 += __shfl_xor_sync(0xffffffffu, a10, s);
            a11 += __shfl_xor_sync(0xffffffffu, a11, s);
            a12 += __shfl_xor_sync(0xffffffffu, a12, s);
            a20 += __shfl_xor_sync(0xffffffffu, a20, s);
            a21 += __shfl_xor_sync(0xffffffffu, a21, s);
            a22 += __shfl_xor_sync(0xffffffffu, a22, s);
        }
        if (lane == 0){
            float* g0 = gb + (bu*3+0)*27 + bv*3;
            float* g1 = gb + (bu*3+1)*27 + bv*3;
            float* g2 = gb + (bu*3+2)*27 + bv*3;
            atomicAdd(g0+0,a00); atomicAdd(g0+1,a01); atomicAdd(g0+2,a02);
            atomicAdd(g1+0,a10); atomicAdd(g1+1,a11); atomicAdd(g1+2,a12);
            atomicAdd(g2+0,a20); atomicAdd(g2+1,a21); atomicAdd(g2+2,a22);
        }
    }
}

// ---------------- K3: per-(batch,head) attention, atomic partial Weff ----------------
__global__ __launch_bounds__(256) void k_attn(const float* __restrict__ w_im1,
                                              const float* __restrict__ w_im2,
                                              const float* __restrict__ w_e,
                                              const float* __restrict__ w_proj,
                                              const float* __restrict__ a1){
    __shared__ float sG[27][27];
    __shared__ float sT[24][9];
    __shared__ float sqq[24];
    __shared__ float skk[24];
    __shared__ float sAt[24][24];
    __shared__ float sWf[2][24];
    __shared__ float swe[24*9];
    int b = blockIdx.x >> 3;
    int h = blockIdx.x & 7;
    int j0 = h*24;
    int tid = threadIdx.x;

    for (int i = tid; i < 729; i += 256){
        int u = i/27, v = i - u*27;
        int lo = u < v ? u : v, hi = u < v ? v : u;
        sG[u][v] = g_gram[b*729 + lo*27 + hi];
    }
    for (int i = tid; i < 216; i += 256) swe[i] = __ldg(w_e + j0*9 + i);
    __syncthreads();

    if (tid < 24){
        int j = j0 + tid;
        float aq[18];
        #pragma unroll
        for (int u = 0; u < 18; u++){
            int base = u/9, tt = u - base*9;
            aq[u] = __ldg(w_im1 + j*2 + base) * __ldg(w_im2 + j*9 + tt);
        }
        float qq = 0.f;
        #pragma unroll
        for (int u = 0; u < 18; u++){
            float s = 0.f;
            #pragma unroll
            for (int v = 0; v < 18; v++) s += aq[v]*sG[u][v];
            qq += aq[u]*s;
        }
        sqq[tid] = qq;
        #pragma unroll
        for (int tt = 0; tt < 9; tt++){
            float s = 0.f;
            #pragma unroll
            for (int u = 0; u < 18; u++) s += aq[u]*sG[u][18+tt];
            sT[tid][tt] = s;
        }
    } else if (tid >= 128 && tid < 152){
        int d = tid - 128;
        float kk = 0.f;
        #pragma unroll
        for (int t1 = 0; t1 < 9; t1++){
            float s = 0.f;
            #pragma unroll
            for (int t2 = 0; t2 < 9; t2++) s += swe[d*9+t2]*sG[18+t1][18+t2];
            kk += swe[d*9+t1]*s;
        }
        skk[d] = kk;
    }
    __syncthreads();

    float a1h = __ldg(a1 + h);
    for (int i = tid; i < 576; i += 256){
        int c = i / 24, d = i - (i/24)*24;
        float s = 0.f;
        #pragma unroll
        for (int tt = 0; tt < 9; tt++) s += sT[c][tt] * swe[d*9+tt];
        float rq = rsqrtf(fmaxf(sqq[c], 1e-24f));
        float rk = rsqrtf(fmaxf(skk[d], 1e-24f));
        sAt[c][d] = s * a1h * rq * rk;
    }
    __syncthreads();

    if (tid < 24){
        float m = -1e30f;
        #pragma unroll
        for (int d = 0; d < 24; d++) m = fmaxf(m, sAt[tid][d]);
        float ex[24]; float ssum = 0.f;
        #pragma unroll
        for (int d = 0; d < 24; d++){ ex[d] = __expf(sAt[tid][d] - m); ssum += ex[d]; }
        float inv = 1.f/ssum;
        #pragma unroll
        for (int d = 0; d < 24; d++) sAt[tid][d] = ex[d]*inv;
    }
    __syncthreads();

    if (tid < 48){
        int ch = tid / 24, d = tid - (tid/24)*24;
        float s = 0.f;
        #pragma unroll
        for (int c = 0; c < 24; c++) s += __ldg(w_proj + ch*192 + j0 + c) * sAt[c][d];
        sWf[ch][d] = s;
    }
    __syncthreads();

    if (tid < 36){
        int ch = tid / 18, r = tid - (tid/18)*18;
        int base = r / 9, tt = r - (r/9)*9;
        float s = 0.f;
        #pragma unroll
        for (int d = 0; d < 24; d++){
            int jp = j0 + d;
            s += sWf[ch][d] * __ldg(w_im1 + (192+jp)*2 + base) * __ldg(w_im2 + (192+jp)*9 + tt);
        }
        atomicAdd(g_weff + b*36 + tid, s);
    }
}

// ---------------- K4: out = ximg + Weff(*)ximg, then coil-expand (2 px/thread) ----------------
__global__ __launch_bounds__(256) void k_output(const float* __restrict__ sens,
                                                float* __restrict__ out){
    __shared__ float sw[36];
    __shared__ float sX[2][10][66];
    int b   = blockIdx.z;
    int ty0 = blockIdx.y*8, tx0 = blockIdx.x*64;
    int tid = threadIdx.x;
    if (tid < 36) sw[tid] = g_weff[b*36 + tid];
    for (int i = tid; i < 2*10*66; i += 256){
        int pl = i/660; int r = i - pl*660;
        int y = r/66, xx = r - y*66;
        int gy = ty0 + y - 1, gx = tx0 + xx - 1;
        float v = 0.f;
        if (gy >= 0 && gy < Hh && gx >= 0 && gx < Ww) v = g_ximg[(size_t)(b*2+pl)*HW + gy*Ww + gx];
        sX[pl][y][xx] = v;
    }
    __syncthreads();

    int py  = tid >> 5;
    int px2 = (tid & 31)*2;
    float o0a = sX[0][py+1][px2+1], o0b = sX[0][py+1][px2+2];
    float o1a = sX[1][py+1][px2+1], o1b = sX[1][py+1][px2+2];
    #pragma unroll
    for (int base = 0; base < 2; base++){
        #pragma unroll
        for (int dy = 0; dy < 3; dy++){
            float w0 = sX[base][py+dy][px2+0];
            float w1 = sX[base][py+dy][px2+1];
            float w2 = sX[base][py+dy][px2+2];
            float w3 = sX[base][py+dy][px2+3];
            float c00 = sw[0*18 + base*9 + dy*3 + 0];
            float c01 = sw[0*18 + base*9 + dy*3 + 1];
            float c02 = sw[0*18 + base*9 + dy*3 + 2];
            float c10 = sw[1*18 + base*9 + dy*3 + 0];
            float c11 = sw[1*18 + base*9 + dy*3 + 1];
            float c12 = sw[1*18 + base*9 + dy*3 + 2];
            o0a += c00*w0 + c01*w1 + c02*w2;
            o0b += c00*w1 + c01*w2 + c02*w3;
            o1a += c10*w0 + c11*w1 + c12*w2;
            o1b += c10*w1 + c11*w2 + c12*w3;
        }
    }
    int p  = (ty0+py)*Ww + tx0 + px2;   // even
    int h4 = p >> 1;
    const float4* sp = reinterpret_cast<const float4*>(sens) + (size_t)b*COILS*(HW/2) + h4;
    float4*       op = reinterpret_cast<float4*>(out)        + (size_t)b*COILS*(HW/2) + h4;
    #pragma unroll
    for (int c = 0; c < COILS; c++){
        float4 s = __ldg(sp + (size_t)c*(HW/2));
        float4 r;
        r.x = o0a*s.x - o1a*s.y;
        r.y = o0a*s.y + o1a*s.x;
        r.z = o0b*s.z - o1b*s.w;
        r.w = o0b*s.w + o1b*s.z;
        op[(size_t)c*(HW/2)] = r;
    }
}

extern "C" void kernel_launch(void* const* d_in, const int* in_sizes, int n_in,
                              void* d_out, int out_size){
    const float* x      = (const float*)d_in[0];
    const float* e      = (const float*)d_in[1];
    const float* sens   = (const float*)d_in[2];
    const float* w_im1  = (const float*)d_in[3];
    const float* w_im2  = (const float*)d_in[4];
    const float* w_e    = (const float*)d_in[5];
    const float* w_proj = (const float*)d_in[6];
    const float* a1     = (const float*)d_in[7];
    float* out = (float*)d_out;

    k_coil_reduce<<<(Bz*HW/2)/256, 256>>>(x, sens);
    k_gram<<<dim3(Ww/32, Hh/32, Bz), 256>>>(e);
    k_attn<<<Bz*8, 256>>>(w_im1, w_im2, w_e, w_proj, a1);
    k_output<<<dim3(Ww/64, Hh/8, Bz), 256>>>(sens, out);
}

// round 15
// speedup vs baseline: 1.0592x; 1.0592x over previous
#include <cuda_runtime.h>

#define Bz 8
#define Hh 384
#define Ww 384
#define HW (384*384)
#define COILS 16

__device__ float g_ximg[Bz*2*HW];        // (B,2,H,W): real/imag planes
__device__ float g_gram[Bz*27*27];       // per-batch 27x27 Gram (block-upper-triangle valid)
__device__ float g_weff[Bz*2*2*9];       // per-batch effective 2->2 3x3 conv weights

__constant__ unsigned char cPU[45] = {0,0,0,0,0,0,0,0,0, 1,1,1,1,1,1,1,1, 2,2,2,2,2,2,2,
                                      3,3,3,3,3,3, 4,4,4,4,4, 5,5,5,5, 6,6,6, 7,7, 8};
__constant__ unsigned char cPV[45] = {0,1,2,3,4,5,6,7,8, 1,2,3,4,5,6,7,8, 2,3,4,5,6,7,8,
                                      3,4,5,6,7,8, 4,5,6,7,8, 5,6,7,8, 6,7,8, 7,8, 8};

__device__ __forceinline__ void pdl_wait(){
    asm volatile("griddepcontrol.wait;" ::: "memory");
}
__device__ __forceinline__ void pdl_launch_dependents(){
    asm volatile("griddepcontrol.launch_dependents;" ::: "memory");
}

// ------- K1' (fused): coil-combine into smem tile (with halo) + store interior + Gram -------
__global__ __launch_bounds__(256) void k_cgram(const float* __restrict__ x,
                                               const float* __restrict__ sens,
                                               const float* __restrict__ e){
    __shared__ float sm[3*34*37];     // planes: ximg_re, ximg_im, e; 34x34 tile+halo, stride 37
    int b   = blockIdx.z;
    int ty0 = blockIdx.y*32, tx0 = blockIdx.x*32;
    int tid = threadIdx.x;

    if (blockIdx.x == 0 && blockIdx.y == 0 && tid < 36) g_weff[b*36 + tid] = 0.f;

    const float2* xb = reinterpret_cast<const float2*>(x)    + (size_t)b*COILS*HW;
    const float2* sb = reinterpret_cast<const float2*>(sens) + (size_t)b*COILS*HW;

    for (int i = tid; i < 34*34; i += 256){
        int y = i / 34, xx = i - y*34;
        int gy = ty0 + y - 1, gx = tx0 + xx - 1;
        float re = 0.f, im = 0.f, ev = 0.f;
        bool in = (gy >= 0 && gy < Hh && gx >= 0 && gx < Ww);
        if (in){
            int p = gy*Ww + gx;
            const float2* xp = xb + p;
            const float2* sp = sb + p;
            #pragma unroll
            for (int c = 0; c < COILS; c++){
                float2 a = __ldg(xp + (size_t)c*HW);
                float2 s = __ldg(sp + (size_t)c*HW);
                re += a.x*s.x + a.y*s.y;   // cmul(a, conj(s)).re
                im += a.y*s.x - a.x*s.y;   // cmul(a, conj(s)).im
            }
            ev = __ldg(e + (size_t)b*HW + p);
        }
        sm[0*1258 + y*37 + xx] = re;
        sm[1*1258 + y*37 + xx] = im;
        sm[2*1258 + y*37 + xx] = ev;
        if (in && y >= 1 && y < 33 && xx >= 1 && xx < 33){
            int p = gy*Ww + gx;
            g_ximg[(size_t)(b*2+0)*HW + p] = re;
            g_ximg[(size_t)(b*2+1)*HW + p] = im;
        }
    }
    __syncthreads();

    int lane = tid & 31;
    float* gb = g_gram + b*729;
    // 1440 tasks = 45 block-pairs x 32 rows; each warp-iteration owns exactly one pair.
    for (int task = tid; task < 1440; task += 256){
        int pair = task >> 5;
        int y    = task & 31;
        int bu = cPU[pair], bv = cPV[pair];
        const float* ru = sm + (bu/3)*1258 + (y + (bu%3))*37;
        const float* rv = sm + (bv/3)*1258 + (y + (bv%3))*37;
        float u0 = ru[0], u1 = ru[1];
        float v0 = rv[0], v1 = rv[1];
        float a00=0,a01=0,a02=0,a10=0,a11=0,a12=0,a20=0,a21=0,a22=0;
        #pragma unroll
        for (int xx = 0; xx < 32; xx++){
            float u2 = ru[xx+2], v2 = rv[xx+2];
            a00 += u0*v0; a01 += u0*v1; a02 += u0*v2;
            a10 += u1*v0; a11 += u1*v1; a12 += u1*v2;
            a20 += u2*v0; a21 += u2*v1; a22 += u2*v2;
            u0 = u1; u1 = u2; v0 = v1; v1 = v2;
        }
        #pragma unroll
        for (int s = 16; s > 0; s >>= 1){
            a00 += __shfl_xor_sync(0xffffffffu, a00, s);
            a01 += __shfl_xor_sync(0xffffffffu, a01, s);
            a02 += __shfl_xor_sync(0xffffffffu, a02, s);
            a10 += __shfl_xor_sync(0xffffffffu, a10, s);
            a11 += __shfl_xor_sync(0xffffffffu, a11, s);
            a12 += __shfl_xor_sync(0xffffffffu, a12, s);
            a20 += __shfl_xor_sync(0xffffffffu, a20, s);
            a21 += __shfl_xor_sync(0xffffffffu, a21, s);
            a22 += __shfl_xor_sync(0xffffffffu, a22, s);
        }
        if (lane == 0){
            float* g0 = gb + (bu*3+0)*27 + bv*3;
            float* g1 = gb + (bu*3+1)*27 + bv*3;
            float* g2 = gb + (bu*3+2)*27 + bv*3;
            atomicAdd(g0+0,a00); atomicAdd(g0+1,a01); atomicAdd(g0+2,a02);
            atomicAdd(g1+0,a10); atomicAdd(g1+1,a11); atomicAdd(g1+2,a12);
            atomicAdd(g2+0,a20); atomicAdd(g2+1,a21); atomicAdd(g2+2,a22);
        }
    }
}

// ---------------- K3: per-(batch,head) attention (PDL secondary of cgram) ----------------
__global__ __launch_bounds__(256) void k_attn(const float* __restrict__ w_im1,
                                              const float* __restrict__ w_im2,
                                              const float* __restrict__ w_e,
                                              const float* __restrict__ w_proj,
                                              const float* __restrict__ a1){
    __shared__ float sG[27][27];
    __shared__ float sT[24][9];
    __shared__ float sqq[24];
    __shared__ float skk[24];
    __shared__ float sAt[24][24];
    __shared__ float sWf[2][24];
    __shared__ float swe[24*9];
    int b = blockIdx.x >> 3;
    int h = blockIdx.x & 7;
    int j0 = h*24;
    int tid = threadIdx.x;

    // pre-dependency phase: weights only (inputs, independent of cgram output)
    for (int i = tid; i < 216; i += 256) swe[i] = __ldg(w_e + j0*9 + i);

    pdl_wait();                 // cgram complete: g_gram/g_weff/g_ximg final
    pdl_launch_dependents();    // now k_output may schedule (ximg is safe to read)

    for (int i = tid; i < 729; i += 256){
        int u = i/27, v = i - u*27;
        int lo = u < v ? u : v, hi = u < v ? v : u;
        sG[u][v] = g_gram[b*729 + lo*27 + hi];
    }
    __syncthreads();

    if (tid < 24){
        int j = j0 + tid;
        float aq[18];
        #pragma unroll
        for (int u = 0; u < 18; u++){
            int base = u/9, tt = u - base*9;
            aq[u] = __ldg(w_im1 + j*2 + base) * __ldg(w_im2 + j*9 + tt);
        }
        float qq = 0.f;
        #pragma unroll
        for (int u = 0; u < 18; u++){
            float s = 0.f;
            #pragma unroll
            for (int v = 0; v < 18; v++) s += aq[v]*sG[u][v];
            qq += aq[u]*s;
        }
        sqq[tid] = qq;
        #pragma unroll
        for (int tt = 0; tt < 9; tt++){
            float s = 0.f;
            #pragma unroll
            for (int u = 0; u < 18; u++) s += aq[u]*sG[u][18+tt];
            sT[tid][tt] = s;
        }
    } else if (tid >= 128 && tid < 152){
        int d = tid - 128;
        float kk = 0.f;
        #pragma unroll
        for (int t1 = 0; t1 < 9; t1++){
            float s = 0.f;
            #pragma unroll
            for (int t2 = 0; t2 < 9; t2++) s += swe[d*9+t2]*sG[18+t1][18+t2];
            kk += swe[d*9+t1]*s;
        }
        skk[d] = kk;
    }
    __syncthreads();

    float a1h = __ldg(a1 + h);
    for (int i = tid; i < 576; i += 256){
        int c = i / 24, d = i - (i/24)*24;
        float s = 0.f;
        #pragma unroll
        for (int tt = 0; tt < 9; tt++) s += sT[c][tt] * swe[d*9+tt];
        float rq = rsqrtf(fmaxf(sqq[c], 1e-24f));
        float rk = rsqrtf(fmaxf(skk[d], 1e-24f));
        sAt[c][d] = s * a1h * rq * rk;
    }
    __syncthreads();

    if (tid < 24){
        float m = -1e30f;
        #pragma unroll
        for (int d = 0; d < 24; d++) m = fmaxf(m, sAt[tid][d]);
        float ex[24]; float ssum = 0.f;
        #pragma unroll
        for (int d = 0; d < 24; d++){ ex[d] = __expf(sAt[tid][d] - m); ssum += ex[d]; }
        float inv = 1.f/ssum;
        #pragma unroll
        for (int d = 0; d < 24; d++) sAt[tid][d] = ex[d]*inv;
    }
    __syncthreads();

    if (tid < 48){
        int ch = tid / 24, d = tid - (tid/24)*24;
        float s = 0.f;
        #pragma unroll
        for (int c = 0; c < 24; c++) s += __ldg(w_proj + ch*192 + j0 + c) * sAt[c][d];
        sWf[ch][d] = s;
    }
    __syncthreads();

    if (tid < 36){
        int ch = tid / 18, r = tid - (tid/18)*18;
        int base = r / 9, tt = r - (r/9)*9;
        float s = 0.f;
        #pragma unroll
        for (int d = 0; d < 24; d++){
            int jp = j0 + d;
            s += sWf[ch][d] * __ldg(w_im1 + (192+jp)*2 + base) * __ldg(w_im2 + (192+jp)*9 + tt);
        }
        atomicAdd(g_weff + b*36 + tid, s);
    }
}

// ---------------- K4: out = ximg + Weff(*)ximg, coil-expand (PDL secondary of attn) ----------------
__global__ __launch_bounds__(256) void k_output(const float* __restrict__ sens,
                                                float* __restrict__ out){
    __shared__ float sw[36];
    __shared__ float sX[2][10][66];
    int b   = blockIdx.z;
    int ty0 = blockIdx.y*8, tx0 = blockIdx.x*64;
    int tid = threadIdx.x;

    // pre-dependency phase: ximg tile (final since before attn started) + sens is input
    for (int i = tid; i < 2*10*66; i += 256){
        int pl = i/660; int r = i - pl*660;
        int y = r/66, xx = r - y*66;
        int gy = ty0 + y - 1, gx = tx0 + xx - 1;
        float v = 0.f;
        if (gy >= 0 && gy < Hh && gx >= 0 && gx < Ww) v = g_ximg[(size_t)(b*2+pl)*HW + gy*Ww + gx];
        sX[pl][y][xx] = v;
    }

    pdl_wait();                 // attn complete: g_weff final
    if (tid < 36) sw[tid] = g_weff[b*36 + tid];
    __syncthreads();

    int py  = tid >> 5;
    int px2 = (tid & 31)*2;
    float o0a = sX[0][py+1][px2+1], o0b = sX[0][py+1][px2+2];
    float o1a = sX[1][py+1][px2+1], o1b = sX[1][py+1][px2+2];
    #pragma unroll
    for (int base = 0; base < 2; base++){
        #pragma unroll
        for (int dy = 0; dy < 3; dy++){
            float w0 = sX[base][py+dy][px2+0];
            float w1 = sX[base][py+dy][px2+1];
            float w2 = sX[base][py+dy][px2+2];
            float w3 = sX[base][py+dy][px2+3];
            float c00 = sw[0*18 + base*9 + dy*3 + 0];
            float c01 = sw[0*18 + base*9 + dy*3 + 1];
            float c02 = sw[0*18 + base*9 + dy*3 + 2];
            float c10 = sw[1*18 + base*9 + dy*3 + 0];
            float c11 = sw[1*18 + base*9 + dy*3 + 1];
            float c12 = sw[1*18 + base*9 + dy*3 + 2];
            o0a += c00*w0 + c01*w1 + c02*w2;
            o0b += c00*w1 + c01*w2 + c02*w3;
            o1a += c10*w0 + c11*w1 + c12*w2;
            o1b += c10*w1 + c11*w2 + c12*w3;
        }
    }
    int p  = (ty0+py)*Ww + tx0 + px2;   // even
    int h4 = p >> 1;
    const float4* sp = reinterpret_cast<const float4*>(sens) + (size_t)b*COILS*(HW/2) + h4;
    float4*       op = reinterpret_cast<float4*>(out)        + (size_t)b*COILS*(HW/2) + h4;
    #pragma unroll
    for (int c = 0; c < COILS; c++){
        float4 s = __ldg(sp + (size_t)c*(HW/2));
        float4 r;
        r.x = o0a*s.x - o1a*s.y;
        r.y = o0a*s.y + o1a*s.x;
        r.z = o0b*s.z - o1b*s.w;
        r.w = o0b*s.w + o1b*s.z;
        op[(size_t)c*(HW/2)] = r;
    }
}

extern "C" void kernel_launch(void* const* d_in, const int* in_sizes, int n_in,
                              void* d_out, int out_size){
    const float* x      = (const float*)d_in[0];
    const float* e      = (const float*)d_in[1];
    const float* sens   = (const float*)d_in[2];
    const float* w_im1  = (const float*)d_in[3];
    const float* w_im2  = (const float*)d_in[4];
    const float* w_e    = (const float*)d_in[5];
    const float* w_proj = (const float*)d_in[6];
    const float* a1     = (const float*)d_in[7];
    float* out = (float*)d_out;

    void* gaddr = nullptr;
    cudaGetSymbolAddress(&gaddr, g_gram);
    cudaMemsetAsync(gaddr, 0, (size_t)Bz*729*sizeof(float), 0);

    k_cgram<<<dim3(Ww/32, Hh/32, Bz), 256>>>(x, sens, e);

    cudaLaunchAttribute at[1];
    at[0].id = cudaLaunchAttributeProgrammaticStreamSerialization;
    at[0].val.programmaticStreamSerializationAllowed = 1;

    {   // k_attn with PDL (overlaps cgram tail; pre-phase loads weights only)
        cudaLaunchConfig_t cfg = {};
        cfg.gridDim  = dim3(Bz*8);
        cfg.blockDim = dim3(256);
        cfg.dynamicSmemBytes = 0;
        cfg.stream = 0;
        cfg.attrs = at;
        cfg.numAttrs = 1;
        cudaLaunchKernelEx(&cfg, k_attn, w_im1, w_im2, w_e, w_proj, a1);
    }
    {   // k_output with PDL (schedules during attn; pre-phase loads ximg tiles)
        cudaLaunchConfig_t cfg = {};
        cfg.gridDim  = dim3(Ww/64, Hh/8, Bz);
        cfg.blockDim = dim3(256);
        cfg.dynamicSmemBytes = 0;
        cfg.stream = 0;
        cfg.attrs = at;
        cfg.numAttrs = 1;
        cudaLaunchKernelEx(&cfg, k_output, sens, out);
    }
}